// round 2
// baseline (speedup 1.0000x reference)
#include <cuda_runtime.h>
#include <math.h>

#define TT 2048
#define DM 768
#define NH 12
#define HD 64

// Scratch (no cudaMalloc allowed)
__device__ float g_q[TT * DM];
__device__ float g_k[TT * DM];
__device__ float g_v[TT * DM];
__device__ float g_o[TT * DM];

// ---------------------------------------------------------------------------
// SGEMM (NT): C[M,N] = A[M,K] @ B[N,K]^T with M=2048 or 2048, N=K=768.
// 64x64 tile, BK=16, 256 threads, 4x4 microtile per thread.
// Optional epilogue: C = (1-lamb)*C + lamb*vi  (for the V projection).
// ---------------------------------------------------------------------------
__global__ __launch_bounds__(256) void gemm_nt(
    const float* __restrict__ A, const float* __restrict__ B,
    float* __restrict__ C, const float* __restrict__ vi,
    const float* __restrict__ lambp)
{
    __shared__ __align__(16) float As[16][68];
    __shared__ __align__(16) float Bs[16][68];

    const int tid = threadIdx.x;
    const int ty = tid >> 4;          // 0..15 (row group)
    const int tx = tid & 15;          // 0..15 (col group)
    const int lr = tid >> 2;          // 0..63 row within tile for loads
    const int lk = (tid & 3) << 2;    // 0,4,8,12 k offset for loads

    const float* Ap = A + (blockIdx.y * 64 + lr) * DM;
    const float* Bp = B + (blockIdx.x * 64 + lr) * DM;

    float acc[4][4] = {};

    for (int k0 = 0; k0 < DM; k0 += 16) {
        float4 av = *(const float4*)(Ap + k0 + lk);
        float4 bv = *(const float4*)(Bp + k0 + lk);
        __syncthreads();
        As[lk + 0][lr] = av.x; As[lk + 1][lr] = av.y;
        As[lk + 2][lr] = av.z; As[lk + 3][lr] = av.w;
        Bs[lk + 0][lr] = bv.x; Bs[lk + 1][lr] = bv.y;
        Bs[lk + 2][lr] = bv.z; Bs[lk + 3][lr] = bv.w;
        __syncthreads();
        #pragma unroll
        for (int kk = 0; kk < 16; kk++) {
            float4 a4 = *(const float4*)&As[kk][ty << 2];
            float4 b4 = *(const float4*)&Bs[kk][tx << 2];
            float a_[4] = {a4.x, a4.y, a4.z, a4.w};
            float b_[4] = {b4.x, b4.y, b4.z, b4.w};
            #pragma unroll
            for (int i = 0; i < 4; i++)
                #pragma unroll
                for (int j = 0; j < 4; j++)
                    acc[i][j] += a_[i] * b_[j];
        }
    }

    const float lb = vi ? *lambp : 0.0f;
    const float one_m_lb = 1.0f - lb;

    #pragma unroll
    for (int i = 0; i < 4; i++) {
        const int row = blockIdx.y * 64 + (ty << 2) + i;
        const int col = blockIdx.x * 64 + (tx << 2);
        float4 c = make_float4(acc[i][0], acc[i][1], acc[i][2], acc[i][3]);
        if (vi) {
            float4 vv = *(const float4*)(vi + row * DM + col);
            c.x = one_m_lb * c.x + lb * vv.x;
            c.y = one_m_lb * c.y + lb * vv.y;
            c.z = one_m_lb * c.z + lb * vv.z;
            c.w = one_m_lb * c.w + lb * vv.w;
        }
        *(float4*)(C + row * DM + col) = c;
    }
}

// ---------------------------------------------------------------------------
// Per-head RMSNorm + RoPE for q and k. grid = T, block = (32, 12).
// lane i owns the rotary pair (d=i, d=i+32); warp shfl reduction for RMS.
// ---------------------------------------------------------------------------
__global__ void rmsrope_kernel()
{
    const int t = blockIdx.x;
    const int h = threadIdx.y;
    const int lane = threadIdx.x;

    // inv_freq = 10000^(-lane/32); angle = t * inv_freq  (fp32, matches jax)
    const float inv = powf(10000.0f, -(float)lane * (1.0f / 32.0f));
    const float ang = (float)t * inv;
    float sn, cs;
    sincosf(ang, &sn, &cs);

    #pragma unroll
    for (int which = 0; which < 2; which++) {
        float* p = (which ? g_k : g_q) + t * DM + h * HD;
        float a = p[lane];
        float b = p[lane + 32];
        float ss = a * a + b * b;
        #pragma unroll
        for (int o = 16; o; o >>= 1)
            ss += __shfl_xor_sync(0xffffffffu, ss, o);
        const float r = rsqrtf(ss * (1.0f / 64.0f) + 1.1920929e-07f);
        a *= r; b *= r;
        p[lane]      =  a * cs + b * sn;
        p[lane + 32] =  b * cs - a * sn;
    }
}

// ---------------------------------------------------------------------------
// Causal flash attention, fp32. grid = (T/64, NH), 256 threads.
// 64x64 q/k tiles, online softmax, 4x4 microtiles.
// ---------------------------------------------------------------------------
#define SMEM_ATTN (4 * 64 * 68 * (int)sizeof(float))

__global__ __launch_bounds__(256) void attn_kernel()
{
    extern __shared__ __align__(16) float sm[];
    float (*Qs)[68] = (float(*)[68])(sm);               // [d][qrow], q pre-scaled
    float (*Ks)[68] = (float(*)[68])(sm + 64 * 68);     // [d][krow]
    float (*Vs)[68] = (float(*)[68])(sm + 2 * 64 * 68); // [krow][d]
    float (*Ps)[68] = (float(*)[68])(sm + 3 * 64 * 68); // [qrow][krow]

    const int qb = (int)gridDim.x - 1 - (int)blockIdx.x;  // big blocks first
    const int h  = blockIdx.y;
    const int tid = threadIdx.x;
    const int ty = tid >> 4;
    const int tx = tid & 15;
    const int lr = tid >> 2;          // 0..63
    const int ld = (tid & 3) << 2;    // 0,4,8,12
    const float scale = 0.125f;       // 1/sqrt(64)

    // Load Q tile (transposed, pre-scaled)
    {
        const float* qp = g_q + (qb * 64 + lr) * DM + h * HD;
        #pragma unroll
        for (int u = 0; u < 4; u++) {
            const int d = ld + (u << 4);
            float4 v4 = *(const float4*)(qp + d);
            Qs[d + 0][lr] = v4.x * scale;
            Qs[d + 1][lr] = v4.y * scale;
            Qs[d + 2][lr] = v4.z * scale;
            Qs[d + 3][lr] = v4.w * scale;
        }
    }

    float acc[4][4] = {};
    float m[4] = {-1e30f, -1e30f, -1e30f, -1e30f};
    float l[4] = {};

    for (int kb = 0; kb <= qb; kb++) {
        const float* kp = g_k + (kb * 64 + lr) * DM + h * HD;
        const float* vp = g_v + (kb * 64 + lr) * DM + h * HD;
        float4 kv[4], wv[4];
        #pragma unroll
        for (int u = 0; u < 4; u++) {
            kv[u] = *(const float4*)(kp + ld + (u << 4));
            wv[u] = *(const float4*)(vp + ld + (u << 4));
        }
        __syncthreads();   // previous tile fully consumed (also covers Qs on kb==0)
        #pragma unroll
        for (int u = 0; u < 4; u++) {
            const int d = ld + (u << 4);
            Ks[d + 0][lr] = kv[u].x; Ks[d + 1][lr] = kv[u].y;
            Ks[d + 2][lr] = kv[u].z; Ks[d + 3][lr] = kv[u].w;
            *(float4*)&Vs[lr][d] = wv[u];
        }
        __syncthreads();

        // scores S = (Q*scale) @ K^T
        float s[4][4] = {};
        #pragma unroll 8
        for (int d = 0; d < 64; d++) {
            float4 a4 = *(const float4*)&Qs[d][ty << 2];
            float4 b4 = *(const float4*)&Ks[d][tx << 2];
            float a_[4] = {a4.x, a4.y, a4.z, a4.w};
            float b_[4] = {b4.x, b4.y, b4.z, b4.w};
            #pragma unroll
            for (int i = 0; i < 4; i++)
                #pragma unroll
                for (int j = 0; j < 4; j++)
                    s[i][j] += a_[i] * b_[j];
        }

        // causal mask on the diagonal tile
        if (kb == qb) {
            #pragma unroll
            for (int i = 0; i < 4; i++)
                #pragma unroll
                for (int j = 0; j < 4; j++)
                    if ((tx << 2) + j > (ty << 2) + i) s[i][j] = -1e30f;
        }

        // online softmax (row reduction across the 16 tx lanes)
        #pragma unroll
        for (int i = 0; i < 4; i++) {
            float mx = fmaxf(fmaxf(s[i][0], s[i][1]), fmaxf(s[i][2], s[i][3]));
            #pragma unroll
            for (int o = 8; o; o >>= 1)
                mx = fmaxf(mx, __shfl_xor_sync(0xffffffffu, mx, o));
            const float nm = fmaxf(m[i], mx);
            const float al = __expf(m[i] - nm);
            float rs = 0.0f;
            #pragma unroll
            for (int j = 0; j < 4; j++) {
                s[i][j] = __expf(s[i][j] - nm);
                rs += s[i][j];
            }
            #pragma unroll
            for (int o = 8; o; o >>= 1)
                rs += __shfl_xor_sync(0xffffffffu, rs, o);
            l[i] = l[i] * al + rs;
            m[i] = nm;
            #pragma unroll
            for (int j = 0; j < 4; j++) acc[i][j] *= al;
            *(float4*)&Ps[(ty << 2) + i][tx << 2] =
                make_float4(s[i][0], s[i][1], s[i][2], s[i][3]);
        }
        __syncthreads();

        // acc += P @ V
        #pragma unroll 4
        for (int kk = 0; kk < 64; kk += 4) {
            float w_[4][4];
            #pragma unroll
            for (int u = 0; u < 4; u++) {
                float4 t4 = *(const float4*)&Vs[kk + u][tx << 2];
                w_[u][0] = t4.x; w_[u][1] = t4.y; w_[u][2] = t4.z; w_[u][3] = t4.w;
            }
            #pragma unroll
            for (int i = 0; i < 4; i++) {
                float4 t4 = *(const float4*)&Ps[(ty << 2) + i][kk];
                const float p0 = t4.x, p1 = t4.y, p2 = t4.z, p3 = t4.w;
                #pragma unroll
                for (int j = 0; j < 4; j++)
                    acc[i][j] += p0 * w_[0][j] + p1 * w_[1][j]
                               + p2 * w_[2][j] + p3 * w_[3][j];
            }
        }
    }

    #pragma unroll
    for (int i = 0; i < 4; i++) {
        const float invl = 1.0f / l[i];
        float4 o4 = make_float4(acc[i][0] * invl, acc[i][1] * invl,
                                acc[i][2] * invl, acc[i][3] * invl);
        *(float4*)(g_o + (qb * 64 + (ty << 2) + i) * DM + h * HD + (tx << 2)) = o4;
    }
}

// ---------------------------------------------------------------------------
extern "C" void kernel_launch(void* const* d_in, const int* in_sizes, int n_in,
                              void* d_out, int out_size)
{
    const float* x    = (const float*)d_in[0];
    const float* vi   = (const float*)d_in[1];
    const float* Wq   = (const float*)d_in[2];
    const float* Wk   = (const float*)d_in[3];
    const float* Wv   = (const float*)d_in[4];
    const float* Wp   = (const float*)d_in[5];
    const float* lamb = (const float*)d_in[6];
    float* out = (float*)d_out;

    float *q, *k, *v, *o;
    cudaGetSymbolAddress((void**)&q, g_q);
    cudaGetSymbolAddress((void**)&k, g_k);
    cudaGetSymbolAddress((void**)&v, g_v);
    cudaGetSymbolAddress((void**)&o, g_o);

    cudaFuncSetAttribute(attn_kernel,
                         cudaFuncAttributeMaxDynamicSharedMemorySize, SMEM_ATTN);

    const dim3 gg(DM / 64, TT / 64);
    gemm_nt<<<gg, 256>>>(x, Wq, q, nullptr, nullptr);
    gemm_nt<<<gg, 256>>>(x, Wk, k, nullptr, nullptr);
    gemm_nt<<<gg, 256>>>(x, Wv, v, vi, lamb);
    rmsrope_kernel<<<TT, dim3(32, 12)>>>();
    attn_kernel<<<dim3(TT / 64, NH), 256, SMEM_ATTN>>>();
    gemm_nt<<<gg, 256>>>(o, Wp, out, nullptr, nullptr);
}

// round 4
// speedup vs baseline: 1.3276x; 1.3276x over previous
#include <cuda_runtime.h>
#include <math.h>
#include <stdint.h>

#define TT 2048
#define DM 768
#define NH 12
#define HD 64

// Scratch (no cudaMalloc allowed)
__device__ float g_q[TT * DM];
__device__ float g_k[TT * DM];
__device__ float g_v[TT * DM];
__device__ float g_o[TT * DM];

// ---------------------------------------------------------------------------
// TF32 helpers
// ---------------------------------------------------------------------------
__device__ __forceinline__ uint32_t f2tf(float f) {
    uint32_t u;
    asm("cvt.rna.tf32.f32 %0, %1;" : "=r"(u) : "f"(f));
    return u;
}

__device__ __forceinline__ void mma_tf32(float* c, const uint32_t* a, const uint32_t* b) {
    asm volatile(
        "mma.sync.aligned.m16n8k8.row.col.f32.tf32.tf32.f32 "
        "{%0,%1,%2,%3}, {%4,%5,%6,%7}, {%8,%9}, {%0,%1,%2,%3};\n"
        : "+f"(c[0]), "+f"(c[1]), "+f"(c[2]), "+f"(c[3])
        : "r"(a[0]), "r"(a[1]), "r"(a[2]), "r"(a[3]), "r"(b[0]), "r"(b[1]));
}

// ---------------------------------------------------------------------------
// TF32 tensor-core GEMM (NT): C[M,N] = A[M,K] @ B[N,K]^T, M=2048, N=K=768.
// Block tile 128x64, BK=16, 256 threads (8 warps, 4x2), warp tile 32x32.
// Optional epilogue: C = (1-lamb)*C + lamb*vi.
// ---------------------------------------------------------------------------
__device__ __forceinline__ void gemm_tf32_body(
    const float* __restrict__ A, const float* __restrict__ B,
    float* __restrict__ C, const float* __restrict__ vi, float lb)
{
    __shared__ uint32_t As[128][20];   // [m][k], pad 20 -> conflict-free frag loads
    __shared__ uint32_t Bs[64][20];    // [n][k]

    const int bm = blockIdx.y, bn = blockIdx.x;
    const int tid = threadIdx.x;
    const int warp = tid >> 5, lane = tid & 31;
    const int gid = lane >> 2, tig = lane & 3;
    const int wm = warp >> 1, wn = warp & 1;

    const int arow = tid >> 1, acol = (tid & 1) << 3;   // 128 rows x 16 k
    const int brow = tid >> 2, bcol = (tid & 3) << 2;   // 64 rows x 16 k

    const float* Ap = A + (bm * 128 + arow) * DM + acol;
    const float* Bp = B + (bn * 64 + brow) * DM + bcol;

    float c[2][4][4] = {};

    float4 av0 = *(const float4*)(Ap);
    float4 av1 = *(const float4*)(Ap + 4);
    float4 bv  = *(const float4*)(Bp);

    for (int k0 = 0; k0 < DM; k0 += 16) {
        __syncthreads();
        As[arow][acol + 0] = f2tf(av0.x);
        As[arow][acol + 1] = f2tf(av0.y);
        As[arow][acol + 2] = f2tf(av0.z);
        As[arow][acol + 3] = f2tf(av0.w);
        As[arow][acol + 4] = f2tf(av1.x);
        As[arow][acol + 5] = f2tf(av1.y);
        As[arow][acol + 6] = f2tf(av1.z);
        As[arow][acol + 7] = f2tf(av1.w);
        Bs[brow][bcol + 0] = f2tf(bv.x);
        Bs[brow][bcol + 1] = f2tf(bv.y);
        Bs[brow][bcol + 2] = f2tf(bv.z);
        Bs[brow][bcol + 3] = f2tf(bv.w);
        __syncthreads();
        if (k0 + 16 < DM) {
            av0 = *(const float4*)(Ap + k0 + 16);
            av1 = *(const float4*)(Ap + k0 + 20);
            bv  = *(const float4*)(Bp + k0 + 16);
        }
        #pragma unroll
        for (int ks = 0; ks < 16; ks += 8) {
            uint32_t af[2][4], bf[4][2];
            #pragma unroll
            for (int i = 0; i < 2; i++) {
                const int m0 = wm * 32 + i * 16;
                af[i][0] = As[m0 + gid][ks + tig];
                af[i][1] = As[m0 + 8 + gid][ks + tig];
                af[i][2] = As[m0 + gid][ks + tig + 4];
                af[i][3] = As[m0 + 8 + gid][ks + tig + 4];
            }
            #pragma unroll
            for (int j = 0; j < 4; j++) {
                const int n0 = wn * 32 + j * 8;
                bf[j][0] = Bs[n0 + gid][ks + tig];
                bf[j][1] = Bs[n0 + gid][ks + tig + 4];
            }
            #pragma unroll
            for (int i = 0; i < 2; i++)
                #pragma unroll
                for (int j = 0; j < 4; j++)
                    mma_tf32(c[i][j], af[i], bf[j]);
        }
    }

    const float oml = 1.0f - lb;
    #pragma unroll
    for (int i = 0; i < 2; i++) {
        #pragma unroll
        for (int j = 0; j < 4; j++) {
            const int r0 = bm * 128 + wm * 32 + i * 16 + gid;
            const int cn = bn * 64 + wn * 32 + j * 8 + (tig << 1);
            float2 p0 = make_float2(c[i][j][0], c[i][j][1]);
            float2 p1 = make_float2(c[i][j][2], c[i][j][3]);
            if (vi) {
                float2 v0 = *(const float2*)(vi + r0 * DM + cn);
                float2 v1 = *(const float2*)(vi + (r0 + 8) * DM + cn);
                p0.x = oml * p0.x + lb * v0.x;
                p0.y = oml * p0.y + lb * v0.y;
                p1.x = oml * p1.x + lb * v1.x;
                p1.y = oml * p1.y + lb * v1.y;
            }
            *(float2*)(C + r0 * DM + cn) = p0;
            *(float2*)(C + (r0 + 8) * DM + cn) = p1;
        }
    }
}

__global__ __launch_bounds__(256) void gemm_qkv(
    const float* __restrict__ x,
    const float* __restrict__ Wq, const float* __restrict__ Wk,
    const float* __restrict__ Wv,
    const float* __restrict__ vi, const float* __restrict__ lambp,
    float* __restrict__ q, float* __restrict__ k, float* __restrict__ v)
{
    const int z = blockIdx.z;
    const float* B = (z == 0) ? Wq : (z == 1) ? Wk : Wv;
    float* C = (z == 0) ? q : (z == 1) ? k : v;
    const float* mix = (z == 2) ? vi : nullptr;
    const float lb = (z == 2) ? *lambp : 0.0f;
    gemm_tf32_body(x, B, C, mix, lb);
}

__global__ __launch_bounds__(256) void gemm_proj(
    const float* __restrict__ A, const float* __restrict__ B,
    float* __restrict__ C)
{
    gemm_tf32_body(A, B, C, nullptr, 0.0f);
}

// ---------------------------------------------------------------------------
// Per-head RMSNorm + RoPE for q and k. grid = T, block = (32, 12).
// ---------------------------------------------------------------------------
__global__ void rmsrope_kernel()
{
    const int t = blockIdx.x;
    const int h = threadIdx.y;
    const int lane = threadIdx.x;

    const float inv = powf(10000.0f, -(float)lane * (1.0f / 32.0f));
    const float ang = (float)t * inv;
    float sn, cs;
    sincosf(ang, &sn, &cs);

    #pragma unroll
    for (int which = 0; which < 2; which++) {
        float* p = (which ? g_k : g_q) + t * DM + h * HD;
        float a = p[lane];
        float b = p[lane + 32];
        float ss = a * a + b * b;
        #pragma unroll
        for (int o = 16; o; o >>= 1)
            ss += __shfl_xor_sync(0xffffffffu, ss, o);
        const float r = rsqrtf(ss * (1.0f / 64.0f) + 1.1920929e-07f);
        a *= r; b *= r;
        p[lane]      =  a * cs + b * sn;
        p[lane + 32] =  b * cs - a * sn;
    }
}

// ---------------------------------------------------------------------------
// Causal flash attention, fp32. grid = (T/64, NH), 256 threads.
// ---------------------------------------------------------------------------
#define SMEM_ATTN (4 * 64 * 68 * (int)sizeof(float))

__global__ __launch_bounds__(256) void attn_kernel()
{
    extern __shared__ __align__(16) float sm[];
    float (*Qs)[68] = (float(*)[68])(sm);
    float (*Ks)[68] = (float(*)[68])(sm + 64 * 68);
    float (*Vs)[68] = (float(*)[68])(sm + 2 * 64 * 68);
    float (*Ps)[68] = (float(*)[68])(sm + 3 * 64 * 68);

    const int qb = (int)gridDim.x - 1 - (int)blockIdx.x;
    const int h  = blockIdx.y;
    const int tid = threadIdx.x;
    const int ty = tid >> 4;
    const int tx = tid & 15;
    const int lr = tid >> 2;
    const int ld = (tid & 3) << 2;
    const float scale = 0.125f;

    {
        const float* qp = g_q + (qb * 64 + lr) * DM + h * HD;
        #pragma unroll
        for (int u = 0; u < 4; u++) {
            const int d = ld + (u << 4);
            float4 v4 = *(const float4*)(qp + d);
            Qs[d + 0][lr] = v4.x * scale;
            Qs[d + 1][lr] = v4.y * scale;
            Qs[d + 2][lr] = v4.z * scale;
            Qs[d + 3][lr] = v4.w * scale;
        }
    }

    float acc[4][4] = {};
    float m[4] = {-1e30f, -1e30f, -1e30f, -1e30f};
    float l[4] = {};

    for (int kb = 0; kb <= qb; kb++) {
        const float* kp = g_k + (kb * 64 + lr) * DM + h * HD;
        const float* vp = g_v + (kb * 64 + lr) * DM + h * HD;
        float4 kv[4], wv[4];
        #pragma unroll
        for (int u = 0; u < 4; u++) {
            kv[u] = *(const float4*)(kp + ld + (u << 4));
            wv[u] = *(const float4*)(vp + ld + (u << 4));
        }
        __syncthreads();
        #pragma unroll
        for (int u = 0; u < 4; u++) {
            const int d = ld + (u << 4);
            Ks[d + 0][lr] = kv[u].x; Ks[d + 1][lr] = kv[u].y;
            Ks[d + 2][lr] = kv[u].z; Ks[d + 3][lr] = kv[u].w;
            *(float4*)&Vs[lr][d] = wv[u];
        }
        __syncthreads();

        float s[4][4] = {};
        #pragma unroll 8
        for (int d = 0; d < 64; d++) {
            float4 a4 = *(const float4*)&Qs[d][ty << 2];
            float4 b4 = *(const float4*)&Ks[d][tx << 2];
            float a_[4] = {a4.x, a4.y, a4.z, a4.w};
            float b_[4] = {b4.x, b4.y, b4.z, b4.w};
            #pragma unroll
            for (int i = 0; i < 4; i++)
                #pragma unroll
                for (int j = 0; j < 4; j++)
                    s[i][j] += a_[i] * b_[j];
        }

        if (kb == qb) {
            #pragma unroll
            for (int i = 0; i < 4; i++)
                #pragma unroll
                for (int j = 0; j < 4; j++)
                    if ((tx << 2) + j > (ty << 2) + i) s[i][j] = -1e30f;
        }

        #pragma unroll
        for (int i = 0; i < 4; i++) {
            float mx = fmaxf(fmaxf(s[i][0], s[i][1]), fmaxf(s[i][2], s[i][3]));
            #pragma unroll
            for (int o = 8; o; o >>= 1)
                mx = fmaxf(mx, __shfl_xor_sync(0xffffffffu, mx, o));
            const float nm = fmaxf(m[i], mx);
            const float al = __expf(m[i] - nm);
            float rs = 0.0f;
            #pragma unroll
            for (int j = 0; j < 4; j++) {
                s[i][j] = __expf(s[i][j] - nm);
                rs += s[i][j];
            }
            #pragma unroll
            for (int o = 8; o; o >>= 1)
                rs += __shfl_xor_sync(0xffffffffu, rs, o);
            l[i] = l[i] * al + rs;
            m[i] = nm;
            #pragma unroll
            for (int j = 0; j < 4; j++) acc[i][j] *= al;
            *(float4*)&Ps[(ty << 2) + i][tx << 2] =
                make_float4(s[i][0], s[i][1], s[i][2], s[i][3]);
        }
        __syncthreads();

        #pragma unroll 4
        for (int kk = 0; kk < 64; kk += 4) {
            float w_[4][4];
            #pragma unroll
            for (int u = 0; u < 4; u++) {
                float4 t4 = *(const float4*)&Vs[kk + u][tx << 2];
                w_[u][0] = t4.x; w_[u][1] = t4.y; w_[u][2] = t4.z; w_[u][3] = t4.w;
            }
            #pragma unroll
            for (int i = 0; i < 4; i++) {
                float4 t4 = *(const float4*)&Ps[(ty << 2) + i][kk];
                const float p0 = t4.x, p1 = t4.y, p2 = t4.z, p3 = t4.w;
                #pragma unroll
                for (int j = 0; j < 4; j++)
                    acc[i][j] += p0 * w_[0][j] + p1 * w_[1][j]
                               + p2 * w_[2][j] + p3 * w_[3][j];
            }
        }
    }

    #pragma unroll
    for (int i = 0; i < 4; i++) {
        const float invl = 1.0f / l[i];
        float4 o4 = make_float4(acc[i][0] * invl, acc[i][1] * invl,
                                acc[i][2] * invl, acc[i][3] * invl);
        *(float4*)(g_o + (qb * 64 + (ty << 2) + i) * DM + h * HD + (tx << 2)) = o4;
    }
}

// ---------------------------------------------------------------------------
extern "C" void kernel_launch(void* const* d_in, const int* in_sizes, int n_in,
                              void* d_out, int out_size)
{
    const float* x    = (const float*)d_in[0];
    const float* vi   = (const float*)d_in[1];
    const float* Wq   = (const float*)d_in[2];
    const float* Wk   = (const float*)d_in[3];
    const float* Wv   = (const float*)d_in[4];
    const float* Wp   = (const float*)d_in[5];
    const float* lamb = (const float*)d_in[6];
    float* out = (float*)d_out;

    float *q, *k, *v, *o;
    cudaGetSymbolAddress((void**)&q, g_q);
    cudaGetSymbolAddress((void**)&k, g_k);
    cudaGetSymbolAddress((void**)&v, g_v);
    cudaGetSymbolAddress((void**)&o, g_o);

    cudaFuncSetAttribute(attn_kernel,
                         cudaFuncAttributeMaxDynamicSharedMemorySize, SMEM_ATTN);

    gemm_qkv<<<dim3(DM / 64, TT / 128, 3), 256>>>(x, Wq, Wk, Wv, vi, lamb, q, k, v);
    rmsrope_kernel<<<TT, dim3(32, 12)>>>();
    attn_kernel<<<dim3(TT / 64, NH), 256, SMEM_ATTN>>>();
    gemm_proj<<<dim3(DM / 64, TT / 128), 256>>>(o, Wp, out);
}

// round 7
// speedup vs baseline: 1.9191x; 1.4455x over previous
#include <cuda_runtime.h>
#include <math.h>
#include <stdint.h>

#define TT 2048
#define DM 768
#define NH 12
#define HD 64

// Scratch (no cudaMalloc allowed)
__device__ float g_q[TT * DM];
__device__ float g_k[TT * DM];
__device__ float g_v[TT * DM];
__device__ float g_o[TT * DM];

// ---------------------------------------------------------------------------
// TF32 helpers
// ---------------------------------------------------------------------------
__device__ __forceinline__ uint32_t f2tf(float f) {
    uint32_t u;
    asm("cvt.rna.tf32.f32 %0, %1;" : "=r"(u) : "f"(f));
    return u;
}

__device__ __forceinline__ void mma_tf32(float* c, const uint32_t* a, const uint32_t* b) {
    asm volatile(
        "mma.sync.aligned.m16n8k8.row.col.f32.tf32.tf32.f32 "
        "{%0,%1,%2,%3}, {%4,%5,%6,%7}, {%8,%9}, {%0,%1,%2,%3};\n"
        : "+f"(c[0]), "+f"(c[1]), "+f"(c[2]), "+f"(c[3])
        : "r"(a[0]), "r"(a[1]), "r"(a[2]), "r"(a[3]), "r"(b[0]), "r"(b[1]));
}

// ---------------------------------------------------------------------------
// TF32 tensor-core GEMM (NT): C[M,N] = A[M,K] @ B[N,K]^T, M=2048, N=K=768.
// Block tile 128x64, BK=16, 256 threads (8 warps, 4x2), warp tile 32x32.
// Optional epilogue: C = (1-lamb)*C + lamb*vi.
// ---------------------------------------------------------------------------
__device__ __forceinline__ void gemm_tf32_body(
    const float* __restrict__ A, const float* __restrict__ B,
    float* __restrict__ C, const float* __restrict__ vi, float lb)
{
    __shared__ uint32_t As[128][20];
    __shared__ uint32_t Bs[64][20];

    const int bm = blockIdx.y, bn = blockIdx.x;
    const int tid = threadIdx.x;
    const int warp = tid >> 5, lane = tid & 31;
    const int gid = lane >> 2, tig = lane & 3;
    const int wm = warp >> 1, wn = warp & 1;

    const int arow = tid >> 1, acol = (tid & 1) << 3;
    const int brow = tid >> 2, bcol = (tid & 3) << 2;

    const float* Ap = A + (bm * 128 + arow) * DM + acol;
    const float* Bp = B + (bn * 64 + brow) * DM + bcol;

    float c[2][4][4] = {};

    float4 av0 = *(const float4*)(Ap);
    float4 av1 = *(const float4*)(Ap + 4);
    float4 bv  = *(const float4*)(Bp);

    for (int k0 = 0; k0 < DM; k0 += 16) {
        __syncthreads();
        As[arow][acol + 0] = f2tf(av0.x);
        As[arow][acol + 1] = f2tf(av0.y);
        As[arow][acol + 2] = f2tf(av0.z);
        As[arow][acol + 3] = f2tf(av0.w);
        As[arow][acol + 4] = f2tf(av1.x);
        As[arow][acol + 5] = f2tf(av1.y);
        As[arow][acol + 6] = f2tf(av1.z);
        As[arow][acol + 7] = f2tf(av1.w);
        Bs[brow][bcol + 0] = f2tf(bv.x);
        Bs[brow][bcol + 1] = f2tf(bv.y);
        Bs[brow][bcol + 2] = f2tf(bv.z);
        Bs[brow][bcol + 3] = f2tf(bv.w);
        __syncthreads();
        if (k0 + 16 < DM) {
            av0 = *(const float4*)(Ap + k0 + 16);
            av1 = *(const float4*)(Ap + k0 + 20);
            bv  = *(const float4*)(Bp + k0 + 16);
        }
        #pragma unroll
        for (int ks = 0; ks < 16; ks += 8) {
            uint32_t af[2][4], bf[4][2];
            #pragma unroll
            for (int i = 0; i < 2; i++) {
                const int m0 = wm * 32 + i * 16;
                af[i][0] = As[m0 + gid][ks + tig];
                af[i][1] = As[m0 + 8 + gid][ks + tig];
                af[i][2] = As[m0 + gid][ks + tig + 4];
                af[i][3] = As[m0 + 8 + gid][ks + tig + 4];
            }
            #pragma unroll
            for (int j = 0; j < 4; j++) {
                const int n0 = wn * 32 + j * 8;
                bf[j][0] = Bs[n0 + gid][ks + tig];
                bf[j][1] = Bs[n0 + gid][ks + tig + 4];
            }
            #pragma unroll
            for (int i = 0; i < 2; i++)
                #pragma unroll
                for (int j = 0; j < 4; j++)
                    mma_tf32(c[i][j], af[i], bf[j]);
        }
    }

    const float oml = 1.0f - lb;
    #pragma unroll
    for (int i = 0; i < 2; i++) {
        #pragma unroll
        for (int j = 0; j < 4; j++) {
            const int r0 = bm * 128 + wm * 32 + i * 16 + gid;
            const int cn = bn * 64 + wn * 32 + j * 8 + (tig << 1);
            float2 p0 = make_float2(c[i][j][0], c[i][j][1]);
            float2 p1 = make_float2(c[i][j][2], c[i][j][3]);
            if (vi) {
                float2 v0 = *(const float2*)(vi + r0 * DM + cn);
                float2 v1 = *(const float2*)(vi + (r0 + 8) * DM + cn);
                p0.x = oml * p0.x + lb * v0.x;
                p0.y = oml * p0.y + lb * v0.y;
                p1.x = oml * p1.x + lb * v1.x;
                p1.y = oml * p1.y + lb * v1.y;
            }
            *(float2*)(C + r0 * DM + cn) = p0;
            *(float2*)(C + (r0 + 8) * DM + cn) = p1;
        }
    }
}

__global__ __launch_bounds__(256) void gemm_qkv(
    const float* __restrict__ x,
    const float* __restrict__ Wq, const float* __restrict__ Wk,
    const float* __restrict__ Wv,
    const float* __restrict__ vi, const float* __restrict__ lambp,
    float* __restrict__ q, float* __restrict__ k, float* __restrict__ v)
{
    const int z = blockIdx.z;
    const float* B = (z == 0) ? Wq : (z == 1) ? Wk : Wv;
    float* C = (z == 0) ? q : (z == 1) ? k : v;
    const float* mix = (z == 2) ? vi : nullptr;
    const float lb = (z == 2) ? *lambp : 0.0f;
    gemm_tf32_body(x, B, C, mix, lb);
}

__global__ __launch_bounds__(256) void gemm_proj(
    const float* __restrict__ A, const float* __restrict__ B,
    float* __restrict__ C)
{
    gemm_tf32_body(A, B, C, nullptr, 0.0f);
}

// ---------------------------------------------------------------------------
// Per-head RMSNorm + RoPE for q and k. grid = T, block = (32, 12).
// ---------------------------------------------------------------------------
__global__ void rmsrope_kernel()
{
    const int t = blockIdx.x;
    const int h = threadIdx.y;
    const int lane = threadIdx.x;

    const float inv = powf(10000.0f, -(float)lane * (1.0f / 32.0f));
    const float ang = (float)t * inv;
    float sn, cs;
    sincosf(ang, &sn, &cs);

    #pragma unroll
    for (int which = 0; which < 2; which++) {
        float* p = (which ? g_k : g_q) + t * DM + h * HD;
        float a = p[lane];
        float b = p[lane + 32];
        float ss = a * a + b * b;
        #pragma unroll
        for (int o = 16; o; o >>= 1)
            ss += __shfl_xor_sync(0xffffffffu, ss, o);
        const float r = rsqrtf(ss * (1.0f / 64.0f) + 1.1920929e-07f);
        a *= r; b *= r;
        p[lane]      =  a * cs + b * sn;
        p[lane + 32] =  b * cs - a * sn;
    }
}

// ---------------------------------------------------------------------------
// Causal flash attention, TF32 tensor cores.
// grid = (T/128, NH) reversed, 256 threads = 8 warps; warp owns 16 q-rows.
// Q tile 128x64, K/V tiles 64x64. Softmax warp-local (quad shuffles).
// smem: Qs[128][68] + Ks[64][68] + Vs[64][68] + Ps[128][68]  (tf32 words)
// ---------------------------------------------------------------------------
#define AP 68
#define SMEM_ATTN ((128 * AP + 64 * AP + 64 * AP + 128 * AP) * 4)

__global__ __launch_bounds__(256) void attn_kernel()
{
    extern __shared__ __align__(16) uint32_t smu[];
    uint32_t (*Qs)[AP] = (uint32_t(*)[AP])(smu);
    uint32_t (*Ks)[AP] = (uint32_t(*)[AP])(smu + 128 * AP);
    uint32_t (*Vs)[AP] = (uint32_t(*)[AP])(smu + 192 * AP);
    uint32_t (*Ps)[AP] = (uint32_t(*)[AP])(smu + 256 * AP);

    const int qb = (int)gridDim.x - 1 - (int)blockIdx.x;   // tall blocks first
    const int h  = blockIdx.y;
    const int tid = threadIdx.x;
    const int wm = tid >> 5;
    const int lane = tid & 31;
    const int gid = lane >> 2, tig = lane & 3;
    const float scale = 0.125f;

    // Load Q tile (pre-scaled, tf32): 2 threads per row, 32 cols each
    {
        const int lr = tid >> 1, lc = (tid & 1) << 5;
        const float* qp = g_q + (qb * 128 + lr) * DM + h * HD + lc;
        #pragma unroll
        for (int u = 0; u < 8; u++) {
            float4 v4 = *(const float4*)(qp + u * 4);
            Qs[lr][lc + u * 4 + 0] = f2tf(v4.x * scale);
            Qs[lr][lc + u * 4 + 1] = f2tf(v4.y * scale);
            Qs[lr][lc + u * 4 + 2] = f2tf(v4.z * scale);
            Qs[lr][lc + u * 4 + 3] = f2tf(v4.w * scale);
        }
    }

    float o[8][4] = {};
    float m0 = -1e30f, m1 = -1e30f, l0 = 0.0f, l1 = 0.0f;

    const int r0g = qb * 128 + wm * 16 + gid;   // global q row (first half)
    const int nkb = 2 * qb + 2;

    for (int kb = 0; kb < nkb; kb++) {
        // load K/V tiles: 4 threads per row, 16 cols each
        {
            const int lr = tid >> 2, lc = (tid & 3) << 4;
            const float* kp = g_k + (kb * 64 + lr) * DM + h * HD + lc;
            const float* vp = g_v + (kb * 64 + lr) * DM + h * HD + lc;
            float4 kv[4], vv[4];
            #pragma unroll
            for (int u = 0; u < 4; u++) {
                kv[u] = *(const float4*)(kp + u * 4);
                vv[u] = *(const float4*)(vp + u * 4);
            }
            __syncthreads();   // previous iteration fully consumed
            #pragma unroll
            for (int u = 0; u < 4; u++) {
                Ks[lr][lc + u * 4 + 0] = f2tf(kv[u].x);
                Ks[lr][lc + u * 4 + 1] = f2tf(kv[u].y);
                Ks[lr][lc + u * 4 + 2] = f2tf(kv[u].z);
                Ks[lr][lc + u * 4 + 3] = f2tf(kv[u].w);
                Vs[lr][lc + u * 4 + 0] = f2tf(vv[u].x);
                Vs[lr][lc + u * 4 + 1] = f2tf(vv[u].y);
                Vs[lr][lc + u * 4 + 2] = f2tf(vv[u].z);
                Vs[lr][lc + u * 4 + 3] = f2tf(vv[u].w);
            }
            __syncthreads();
        }

        // warp entirely below this key tile? (all keys > all rows)
        const bool act = (qb * 128 + wm * 16 + 15) >= kb * 64;
        if (act) {
            // S = Q @ K^T   (warp rows wm*16..+16, all 64 keys)
            float s[8][4] = {};
            #pragma unroll
            for (int ks = 0; ks < 64; ks += 8) {
                uint32_t a[4];
                a[0] = Qs[wm * 16 + gid][ks + tig];
                a[1] = Qs[wm * 16 + 8 + gid][ks + tig];
                a[2] = Qs[wm * 16 + gid][ks + tig + 4];
                a[3] = Qs[wm * 16 + 8 + gid][ks + tig + 4];
                #pragma unroll
                for (int j = 0; j < 8; j++) {
                    uint32_t b[2];
                    b[0] = Ks[j * 8 + gid][ks + tig];
                    b[1] = Ks[j * 8 + gid][ks + tig + 4];
                    mma_tf32(s[j], a, b);
                }
            }

            // causal mask (only tiles straddling/above the diagonal)
            if (kb >= 2 * qb) {
                #pragma unroll
                for (int j = 0; j < 8; j++) {
                    const int c0 = kb * 64 + j * 8 + (tig << 1);
                    if (c0 > r0g)         s[j][0] = -1e30f;
                    if (c0 + 1 > r0g)     s[j][1] = -1e30f;
                    if (c0 > r0g + 8)     s[j][2] = -1e30f;
                    if (c0 + 1 > r0g + 8) s[j][3] = -1e30f;
                }
            }

            // online softmax, rows gid (regs 0,1) and gid+8 (regs 2,3)
            float mx0 = -1e30f, mx1 = -1e30f;
            #pragma unroll
            for (int j = 0; j < 8; j++) {
                mx0 = fmaxf(mx0, fmaxf(s[j][0], s[j][1]));
                mx1 = fmaxf(mx1, fmaxf(s[j][2], s[j][3]));
            }
            #pragma unroll
            for (int off = 1; off <= 2; off <<= 1) {
                mx0 = fmaxf(mx0, __shfl_xor_sync(0xffffffffu, mx0, off));
                mx1 = fmaxf(mx1, __shfl_xor_sync(0xffffffffu, mx1, off));
            }
            const float nm0 = fmaxf(m0, mx0), nm1 = fmaxf(m1, mx1);
            const float al0 = __expf(m0 - nm0), al1 = __expf(m1 - nm1);
            float rs0 = 0.0f, rs1 = 0.0f;
            #pragma unroll
            for (int j = 0; j < 8; j++) {
                s[j][0] = __expf(s[j][0] - nm0);
                s[j][1] = __expf(s[j][1] - nm0);
                s[j][2] = __expf(s[j][2] - nm1);
                s[j][3] = __expf(s[j][3] - nm1);
                rs0 += s[j][0] + s[j][1];
                rs1 += s[j][2] + s[j][3];
            }
            #pragma unroll
            for (int off = 1; off <= 2; off <<= 1) {
                rs0 += __shfl_xor_sync(0xffffffffu, rs0, off);
                rs1 += __shfl_xor_sync(0xffffffffu, rs1, off);
            }
            l0 = l0 * al0 + rs0; m0 = nm0;
            l1 = l1 * al1 + rs1; m1 = nm1;
            #pragma unroll
            for (int j = 0; j < 8; j++) {
                o[j][0] *= al0; o[j][1] *= al0;
                o[j][2] *= al1; o[j][3] *= al1;
            }

            // store P (tf32) — each warp's own 16 rows; consumed only by self
            #pragma unroll
            for (int j = 0; j < 8; j++) {
                const int c = j * 8 + (tig << 1);
                uint2 p0 = make_uint2(f2tf(s[j][0]), f2tf(s[j][1]));
                uint2 p1 = make_uint2(f2tf(s[j][2]), f2tf(s[j][3]));
                *(uint2*)&Ps[wm * 16 + gid][c] = p0;
                *(uint2*)&Ps[wm * 16 + 8 + gid][c] = p1;
            }

            // O += P @ V   (no sync needed: self-produced P, V synced above)
            #pragma unroll
            for (int ks = 0; ks < 64; ks += 8) {
                uint32_t a[4];
                a[0] = Ps[wm * 16 + gid][ks + tig];
                a[1] = Ps[wm * 16 + 8 + gid][ks + tig];
                a[2] = Ps[wm * 16 + gid][ks + tig + 4];
                a[3] = Ps[wm * 16 + 8 + gid][ks + tig + 4];
                #pragma unroll
                for (int j = 0; j < 8; j++) {
                    uint32_t b[2];
                    b[0] = Vs[ks + tig][j * 8 + gid];
                    b[1] = Vs[ks + tig + 4][j * 8 + gid];
                    mma_tf32(o[j], a, b);
                }
            }
        }
    }

    // write output
    const float inv0 = 1.0f / l0, inv1 = 1.0f / l1;
    #pragma unroll
    for (int j = 0; j < 8; j++) {
        const int c = h * HD + j * 8 + (tig << 1);
        const int r = qb * 128 + wm * 16 + gid;
        *(float2*)(g_o + r * DM + c) = make_float2(o[j][0] * inv0, o[j][1] * inv0);
        *(float2*)(g_o + (r + 8) * DM + c) = make_float2(o[j][2] * inv1, o[j][3] * inv1);
    }
}

// ---------------------------------------------------------------------------
extern "C" void kernel_launch(void* const* d_in, const int* in_sizes, int n_in,
                              void* d_out, int out_size)
{
    const float* x    = (const float*)d_in[0];
    const float* vi   = (const float*)d_in[1];
    const float* Wq   = (const float*)d_in[2];
    const float* Wk   = (const float*)d_in[3];
    const float* Wv   = (const float*)d_in[4];
    const float* Wp   = (const float*)d_in[5];
    const float* lamb = (const float*)d_in[6];
    float* out = (float*)d_out;

    float *q, *k, *v, *o;
    cudaGetSymbolAddress((void**)&q, g_q);
    cudaGetSymbolAddress((void**)&k, g_k);
    cudaGetSymbolAddress((void**)&v, g_v);
    cudaGetSymbolAddress((void**)&o, g_o);

    cudaFuncSetAttribute(attn_kernel,
                         cudaFuncAttributeMaxDynamicSharedMemorySize, SMEM_ATTN);

    gemm_qkv<<<dim3(DM / 64, TT / 128, 3), 256>>>(x, Wq, Wk, Wv, vi, lamb, q, k, v);
    rmsrope_kernel<<<TT, dim3(32, 12)>>>();
    attn_kernel<<<dim3(TT / 128, NH), 256, SMEM_ATTN>>>();
    gemm_proj<<<dim3(DM / 64, TT / 128), 256>>>(o, Wp, out);
}